// round 14
// baseline (speedup 1.0000x reference)
#include <cuda_runtime.h>
#include <cuda_fp16.h>
#include <cstdint>

#define B_TOT 16384
#define IN_D  64
#define N_R   128
#define OUT_D 32
#define W_COLS ((IN_D + 1) * N_R)   // 8320

#define N_CHUNK 16
#define RC 8
#define M_CTA 64

// ---------------- device scratch ---------------------------------------
__device__ float g_K0[N_R];                     // sum_i s*c^2
__device__ unsigned int g_Bf[N_CHUNK * 8192];   // pre-swizzled fp16 W tiles
__device__ unsigned int g_WH[2048];             // Wf fp16: 2 halves x [32 o][64 rk]
__device__ unsigned int g_LT[8 * 2048];         // logits tables: 8 stages x 8KB

// ---------------- helpers ------------------------------------------------
#define SWZ(x) ((x) ^ (((x) >> 3) & 0x70))
#define FR_STRIDE 136

__device__ __forceinline__ uint32_t smem_u32(const void* p) {
    uint32_t a;
    asm("{ .reg .u64 t; cvta.to.shared.u64 t, %1; cvt.u32.u64 %0, t; }"
        : "=r"(a) : "l"(p));
    return a;
}
__device__ __forceinline__ void cp16(uint32_t dst, const void* src) {
    uint64_t g;
    asm("cvta.to.global.u64 %0, %1;" : "=l"(g) : "l"(src));
    asm volatile("cp.async.cg.shared.global [%0], [%1], 16;"
                 :: "r"(dst), "l"(g) : "memory");
}
#define CP_COMMIT() asm volatile("cp.async.commit_group;" ::: "memory")
#define CP_WAIT0()  asm volatile("cp.async.wait_group 0;" ::: "memory")

#define LDSM4(r, a) \
    asm volatile("ldmatrix.sync.aligned.m8n8.x4.shared.b16 {%0,%1,%2,%3}, [%4];" \
        : "=r"((r)[0]), "=r"((r)[1]), "=r"((r)[2]), "=r"((r)[3]) : "r"(a))

#define MMA(d, a, b0, b1) \
    asm volatile("mma.sync.aligned.m16n8k16.row.col.f32.f16.f16.f32 " \
        "{%0,%1,%2,%3},{%4,%5,%6,%7},{%8,%9},{%0,%1,%2,%3};" \
        : "+f"((d)[0]), "+f"((d)[1]), "+f"((d)[2]), "+f"((d)[3]) \
        : "r"((a)[0]), "r"((a)[1]), "r"((a)[2]), "r"((a)[3]), \
          "r"(b0), "r"(b1))

// first-touch MMA: d = a*b + 0
#define MMA_Z(d, a, b0, b1) \
    asm volatile("mma.sync.aligned.m16n8k16.row.col.f32.f16.f16.f32 " \
        "{%0,%1,%2,%3},{%4,%5,%6,%7},{%8,%9},{%10,%10,%10,%10};" \
        : "=f"((d)[0]), "=f"((d)[1]), "=f"((d)[2]), "=f"((d)[3]) \
        : "r"((a)[0]), "r"((a)[1]), "r"((a)[2]), "r"((a)[3]), \
          "r"(b0), "r"(b1), "f"(0.0f))

__device__ __forceinline__ unsigned int pack_h2(__half a, __half b) {
    return (unsigned int)__half_as_ushort(a)
         | ((unsigned int)__half_as_ushort(b) << 16);
}

// ---------------- merged prep kernel --------------------------------------
// blocks [0,512): W tiles; [512,520): WfH; [520,584): logits; [584,712): k0
__global__ void __launch_bounds__(256) prep_all(const float* __restrict__ W,
                                                const float* __restrict__ centers,
                                                const float* __restrict__ sigmas) {
    int b = blockIdx.x, tid = threadIdx.x;
    if (b < 512) {
        int idx = b * 256 + tid;            // uint index in [0, 131072)
        int c   = idx >> 13;                // chunk 0..15
        int rem = idx & 8191;               // byte_off = rem*4 = n*128 + k2*4
        int n   = rem >> 5, k2 = rem & 31;  // n 0..255
        int rc  = n >> 5,   o  = n & 31;
        int r   = c * RC + rc;
        int k   = k2 * 2;
        float v0 = W[o * W_COLS + r * IN_D + k];
        float v1 = W[o * W_COLS + r * IN_D + k + 1];
        unsigned int sw = SWZ((unsigned)(rem * 4));
        g_Bf[c * 8192 + (sw >> 2)] = pack_h2(__float2half_rn(v0), __float2half_rn(v1));
    } else if (b < 520) {
        int idx = (b - 512) * 256 + tid;    // [0, 2048)
        int h   = idx >> 10;
        int rem = idx & 1023;
        int o   = rem >> 5, rk2 = rem & 31;
        int r   = h * 64 + rk2 * 2;
        float v0 = W[o * W_COLS + IN_D * N_R + r];
        float v1 = W[o * W_COLS + IN_D * N_R + r + 1];
        unsigned int sw = SWZ((unsigned)(o * 128 + rk2 * 4));
        g_WH[h * 1024 + (sw >> 2)] = pack_h2(__float2half_rn(v0), __float2half_rn(v1));
    } else if (b < 584) {
        int idx = (b - 520) * 256 + tid;    // [0, 16384)
        int s   = idx >> 11;                // stage = tau*2 + half
        int rem = idx & 2047;
        int rr  = rem >> 5, k2 = rem & 31;
        int tau = s >> 1,  h  = s & 1;
        int r   = h * 64 + rr;
        __half vv[2];
#pragma unroll
        for (int e = 0; e < 2; ++e) {
            int i = k2 * 2 + e;
            float sg = sigmas[i * N_R + r];
            float c  = centers[i * N_R + r];
            float s_ = 0.5f / (sg * sg) + 1e-8f;
            float c2 = 2.f * s_ * c;
            if (tau == 0)      vv[e] = __float2half_rn(-s_);
            else if (tau == 1) {
                __half vh = __float2half_rn(-s_);
                vv[e] = __float2half_rn(-s_ - __half2float(vh));
            } else if (tau == 2) vv[e] = __float2half_rn(c2);
            else {
                __half vh = __float2half_rn(c2);
                vv[e] = __float2half_rn(c2 - __half2float(vh));
            }
        }
        g_LT[s * 2048 + (SWZ((unsigned)(rem * 4)) >> 2)] = pack_h2(vv[0], vv[1]);
    } else {
        int r = b - 584;                    // one rule per block
        __shared__ float red[64];
        if (tid < 64) {
            int i = tid;
            float sg = sigmas[i * N_R + r];
            float c  = centers[i * N_R + r];
            float s_ = 0.5f / (sg * sg) + 1e-8f;
            red[i] = s_ * c * c;
        }
        __syncthreads();
        if (tid == 0) {
            float k0 = 0.f;
#pragma unroll
            for (int i = 0; i < 64; ++i) k0 += red[i];
            g_K0[r] = k0;
        }
    }
}

// ---------------- fused kernel -------------------------------------------
// smem map (bytes):
//  [0,8192)         T_xh (A tile, live whole kernel); epilogue: red
//  [8192,43008)     T_qh/T_ql/T_xl during logits; then frs fp32 [64][136]
//  [43008,108544)   logits: LT all 8 stages (64K)
//                   main:   B 2x32K
//                   epilogue: FH fp16 2x8K [43008,59392) + WH 2x4K [59392,67584)
//  [108544,109056)  K0 [128] fp32
#define SM_XH 0
#define SM_QH 8192
#define SM_QL 16384
#define SM_XL 24576
#define SM_FR 8192
#define SM_LT 43008
#define SM_B  43008
#define SM_FH 43008
#define SM_WH 59392
#define SM_K0 108544
#define SMEM_TOTAL 109056

__global__ void __launch_bounds__(128) kfused(const float* __restrict__ X,
                                              const float* __restrict__ bias,
                                              float* __restrict__ out,
                                              float* __restrict__ frs) {
    extern __shared__ __align__(1024) char smem[];
    uint32_t sb = smem_u32(smem);
    int tid = threadIdx.x, wid = tid >> 5, lane = tid & 31;
    int bBase = blockIdx.x * M_CTA;

    int lrow = lane & 15, lcol = (lane >> 4) << 4;
    int oc = (lane & 3) << 1;
    int w16 = wid << 4;

    // ---- phase 1: stage ALL logits tables (64K) + K0; build feature tiles
    for (int i = tid; i < 4096; i += 128)
        cp16(sb + SM_LT + i * 16, (const char*)g_LT + i * 16);
    if (tid < 32) cp16(sb + SM_K0 + tid * 16, (const char*)g_K0 + tid * 16);
    CP_COMMIT();

    for (int idx = tid; idx < 1024; idx += 128) {
        int row = idx >> 4, q = idx & 15;
        float4 v = ((const float4*)(X + (size_t)(bBase + row) * IN_D))[q];
        __half xh[4], xl[4], qh[4], ql[4];
#pragma unroll
        for (int e = 0; e < 4; ++e) {
            float x = (&v.x)[e];
            xh[e] = __float2half_rn(x);
            xl[e] = __float2half_rn(x - __half2float(xh[e]));
            float qf = x * x;
            qh[e] = __float2half_rn(qf);
            ql[e] = __float2half_rn(qf - __half2float(qh[e]));
        }
        unsigned int sw = SWZ((unsigned)(row * 128 + q * 8));
        *(uint2*)(smem + SM_XH + sw) = make_uint2(pack_h2(xh[0], xh[1]), pack_h2(xh[2], xh[3]));
        *(uint2*)(smem + SM_XL + sw) = make_uint2(pack_h2(xl[0], xl[1]), pack_h2(xl[2], xl[3]));
        *(uint2*)(smem + SM_QH + sw) = make_uint2(pack_h2(qh[0], qh[1]), pack_h2(qh[2], qh[3]));
        *(uint2*)(smem + SM_QL + sw) = make_uint2(pack_h2(ql[0], ql[1]), pack_h2(ql[2], ql[3]));
    }
    CP_WAIT0();
    __syncthreads();

    // ---- phase 2: logits via tensor cores — no syncs, all tables resident
    float dl[16][4];
#pragma unroll
    for (int t = 0; t < 16; ++t)
        dl[t][0] = dl[t][1] = dl[t][2] = dl[t][3] = 0.f;

#pragma unroll
    for (int j = 0; j < 8; ++j) {
        const int tau = j >> 1, h = j & 1;
        const int np = (tau == 0 || tau == 2) ? 2 : 1;
        const uint32_t p0 = (tau < 2) ? SM_QH : SM_XH;
        const uint32_t p1 = (tau == 0) ? SM_QL : SM_XL;
        uint32_t bufS = sb + SM_LT + j * 8192;

#pragma unroll
        for (int ks = 0; ks < 4; ++ks) {
            int col = ks * 32 + lcol;
            uint32_t bF[4][4];
#pragma unroll
            for (int jj = 0; jj < 4; ++jj)
                LDSM4(bF[jj], bufS + SWZ((unsigned)((jj * 16 + lrow) * 128 + col)));
            uint32_t aFr[4];
            LDSM4(aFr, sb + p0 + SWZ((unsigned)((w16 + lrow) * 128 + col)));
#pragma unroll
            for (int jj = 0; jj < 4; ++jj) {
                MMA(dl[h * 8 + 2 * jj],     aFr, bF[jj][0], bF[jj][2]);
                MMA(dl[h * 8 + 2 * jj + 1], aFr, bF[jj][1], bF[jj][3]);
            }
            if (np == 2) {
                uint32_t aF2[4];
                LDSM4(aF2, sb + p1 + SWZ((unsigned)((w16 + lrow) * 128 + col)));
#pragma unroll
                for (int jj = 0; jj < 4; ++jj) {
                    MMA(dl[h * 8 + 2 * jj],     aF2, bF[jj][0], bF[jj][2]);
                    MMA(dl[h * 8 + 2 * jj + 1], aF2, bF[jj][1], bF[jj][3]);
                }
            }
        }
    }
    __syncthreads();                // all LT reads done before B overwrite

    // ---- phase 2.5: issue chunk0 cp.async (32K, overlaps softmax)
    for (int i = tid; i < 2048; i += 128) cp16(sb + SM_B + i * 16, (const char*)g_Bf + i * 16);
    CP_COMMIT();

    // ---- phase 3: softmax on fragments -> frs fp32 (smem + gmem)
    {
        const float* k0p = (const float*)(smem + SM_K0);
        float mlo = -1e30f, mhi = -1e30f;
#pragma unroll
        for (int t = 0; t < 16; ++t) {
            float2 k2 = *(const float2*)(k0p + t * 8 + oc);
            dl[t][0] -= k2.x; dl[t][1] -= k2.y;
            dl[t][2] -= k2.x; dl[t][3] -= k2.y;
            mlo = fmaxf(mlo, fmaxf(dl[t][0], dl[t][1]));
            mhi = fmaxf(mhi, fmaxf(dl[t][2], dl[t][3]));
        }
#pragma unroll
        for (int off = 1; off < 4; off <<= 1) {
            mlo = fmaxf(mlo, __shfl_xor_sync(0xffffffffu, mlo, off));
            mhi = fmaxf(mhi, __shfl_xor_sync(0xffffffffu, mhi, off));
        }
        float slo = 0.f, shi = 0.f;
#pragma unroll
        for (int t = 0; t < 16; ++t) {
            dl[t][0] = __expf(dl[t][0] - mlo); dl[t][1] = __expf(dl[t][1] - mlo);
            dl[t][2] = __expf(dl[t][2] - mhi); dl[t][3] = __expf(dl[t][3] - mhi);
            slo += dl[t][0] + dl[t][1];
            shi += dl[t][2] + dl[t][3];
        }
#pragma unroll
        for (int off = 1; off < 4; off <<= 1) {
            slo += __shfl_xor_sync(0xffffffffu, slo, off);
            shi += __shfl_xor_sync(0xffffffffu, shi, off);
        }
        float ilo = 1.f / slo, ihi = 1.f / shi;
        int rlo = w16 + (lane >> 2), rhi = rlo + 8;
        float* sFR = (float*)(smem + SM_FR);
#pragma unroll
        for (int t = 0; t < 16; ++t) {
            float2 flo = make_float2(dl[t][0] * ilo, dl[t][1] * ilo);
            float2 fhi = make_float2(dl[t][2] * ihi, dl[t][3] * ihi);
            *(float2*)(sFR + rlo * FR_STRIDE + t * 8 + oc) = flo;
            *(float2*)(sFR + rhi * FR_STRIDE + t * 8 + oc) = fhi;
            *(float2*)(frs + (size_t)(bBase + rlo) * N_R + t * 8 + oc) = flo;
            *(float2*)(frs + (size_t)(bBase + rhi) * N_R + t * 8 + oc) = fhi;
        }
    }
    CP_WAIT0();                     // chunk0 landed
    __syncthreads();

    // ---- main loop: 16 chunks of 8 rules; tp-scoped d; 1-IADD addressing
    int mq = wid >> 1, nq = wid & 1;
    int rm = mq * 32, nb = nq * 128;

    uint32_t aF[2][4][4];
#pragma unroll
    for (int mt = 0; mt < 2; ++mt)
#pragma unroll
        for (int ks = 0; ks < 4; ++ks) {
            uint32_t offA = SWZ((unsigned)((rm + mt * 16 + lrow) * 128 + ks * 32 + lcol));
            LDSM4(aF[mt][ks], sb + SM_XH + offA);
        }
    // closed-form swizzled column offsets (rows are 128B-aligned)
    uint32_t colS[4];
    {
        unsigned xr = ((unsigned)(lrow & 7)) << 4;
#pragma unroll
        for (int ks = 0; ks < 4; ++ks)
            colS[ks] = ((unsigned)(ks * 32 + lcol)) ^ xr;
    }
    uint32_t rowB0 = (unsigned)(nb + lrow) * 128;

    float acc[4][4][2];
#pragma unroll
    for (int a = 0; a < 4; ++a)
#pragma unroll
        for (int b = 0; b < 4; ++b) acc[a][b][0] = acc[a][b][1] = 0.f;

    const float* sFR = (const float*)(smem + SM_FR);

    for (int c = 0; c < N_CHUNK; ++c) {
        int cur = c & 1, nxt = cur ^ 1;

        if (c + 1 < N_CHUNK) {
            const char* gsrc = (const char*)(g_Bf + (c + 1) * 8192);
            uint32_t dd = sb + SM_B + nxt * 32768;
            for (int i = tid; i < 2048; i += 128) cp16(dd + i * 16, gsrc + i * 16);
        }
        CP_COMMIT();

        // firing levels: this warp's 4 rules x 4 row-positions
        float4 f4[2][2];
#pragma unroll
        for (int mt = 0; mt < 2; ++mt)
#pragma unroll
            for (int h = 0; h < 2; ++h) {
                int row = rm + mt * 16 + (lane >> 2) + h * 8;
                f4[mt][h] = *(const float4*)(sFR + row * FR_STRIDE + c * RC + nq * 4);
            }

        uint32_t bufB = sb + SM_B + cur * 32768 + rowB0;
#pragma unroll
        for (int tp = 0; tp < 8; ++tp) {
            float d[2][2][4];
#pragma unroll
            for (int ks = 0; ks < 4; ++ks) {
                uint32_t bH[4];
                LDSM4(bH, bufB + tp * 2048 + colS[ks]);
#pragma unroll
                for (int mt = 0; mt < 2; ++mt) {
                    if (ks == 0) {
                        MMA_Z(d[mt][0], aF[mt][ks], bH[0], bH[2]);
                        MMA_Z(d[mt][1], aF[mt][ks], bH[1], bH[3]);
                    } else {
                        MMA(d[mt][0], aF[mt][ks], bH[0], bH[2]);
                        MMA(d[mt][1], aF[mt][ks], bH[1], bH[3]);
                    }
                }
            }
            // contract with firing level for this tp's rule
            const int rs = tp >> 1;
#pragma unroll
            for (int mt = 0; mt < 2; ++mt)
#pragma unroll
                for (int n8 = 0; n8 < 2; ++n8) {
                    int op = ((tp & 1) << 1) + n8;
#pragma unroll
                    for (int h = 0; h < 2; ++h) {
                        float fl = (&f4[mt][h].x)[rs];
                        acc[mt * 2 + h][op][0] = fmaf(fl, d[mt][n8][2 * h],     acc[mt * 2 + h][op][0]);
                        acc[mt * 2 + h][op][1] = fmaf(fl, d[mt][n8][2 * h + 1], acc[mt * 2 + h][op][1]);
                    }
                }
        }

        CP_WAIT0();
        __syncthreads();
    }

    // ---- epilogue A: rebuild FH (fp16 frs) + load WH into dead B region
    for (int i = tid; i < 512; i += 128)
        cp16(sb + SM_WH + i * 16, (const char*)g_WH + i * 16);
    CP_COMMIT();
    {
        for (int i = tid; i < 4096; i += 128) {
            int h   = i >> 11;
            int rem = i & 2047;
            int row = rem >> 5, rk2 = rem & 31;
            float2 fv = *(const float2*)(sFR + row * FR_STRIDE + h * 64 + rk2 * 2);
            *(uint32_t*)(smem + SM_FH + h * 8192 + SWZ((unsigned)(row * 128 + rk2 * 4))) =
                pack_h2(__float2half_rn(fv.x), __float2half_rn(fv.y));
        }
    }
    CP_WAIT0();
    __syncthreads();

    // ---- epilogue B: rule-bias GEMM  acc += frs_h(nq) @ WfH(nq)
    {
        uint32_t fhBase = sb + SM_FH + nq * 8192;
        uint32_t whBase = sb + SM_WH + nq * 4096;
        float dW[2][2][2][4];
#pragma unroll
        for (int ks = 0; ks < 4; ++ks) {
            uint32_t aFr[2][4];
#pragma unroll
            for (int mt = 0; mt < 2; ++mt)
                LDSM4(aFr[mt], fhBase + SWZ((unsigned)((rm + mt * 16 + lrow) * 128 + ks * 32 + lcol)));
#pragma unroll
            for (int tp = 0; tp < 2; ++tp) {
                uint32_t bW[4];
                LDSM4(bW, whBase + SWZ((unsigned)((tp * 16 + lrow) * 128 + ks * 32 + lcol)));
#pragma unroll
                for (int mt = 0; mt < 2; ++mt) {
                    if (ks == 0) {
                        MMA_Z(dW[mt][tp][0], aFr[mt], bW[0], bW[2]);
                        MMA_Z(dW[mt][tp][1], aFr[mt], bW[1], bW[3]);
                    } else {
                        MMA(dW[mt][tp][0], aFr[mt], bW[0], bW[2]);
                        MMA(dW[mt][tp][1], aFr[mt], bW[1], bW[3]);
                    }
                }
            }
        }
#pragma unroll
        for (int mt = 0; mt < 2; ++mt)
#pragma unroll
            for (int tp = 0; tp < 2; ++tp)
#pragma unroll
                for (int n8 = 0; n8 < 2; ++n8)
#pragma unroll
                    for (int h = 0; h < 2; ++h) {
                        acc[mt * 2 + h][tp * 2 + n8][0] += dW[mt][tp][n8][2 * h];
                        acc[mt * 2 + h][tp * 2 + n8][1] += dW[mt][tp][n8][2 * h + 1];
                    }
    }

    // ---- epilogue C: reduce nq pair via smem (T_xh dead), + bias, store
    __syncthreads();
    float* red = (float*)smem;            // [64][32] fp32 = 8 KB
    if (nq == 1) {
#pragma unroll
        for (int mt = 0; mt < 2; ++mt)
#pragma unroll
            for (int h = 0; h < 2; ++h) {
                int row = rm + mt * 16 + (lane >> 2) + h * 8;
#pragma unroll
                for (int op = 0; op < 4; ++op)
                    *(float2*)(red + row * 32 + op * 8 + oc) =
                        make_float2(acc[mt * 2 + h][op][0], acc[mt * 2 + h][op][1]);
            }
    }
    __syncthreads();
    if (nq == 0) {
        float2 b2[4];
#pragma unroll
        for (int op = 0; op < 4; ++op)
            b2[op] = *(const float2*)(bias + op * 8 + oc);
#pragma unroll
        for (int mt = 0; mt < 2; ++mt)
#pragma unroll
            for (int h = 0; h < 2; ++h) {
                int row = rm + mt * 16 + (lane >> 2) + h * 8;
#pragma unroll
                for (int op = 0; op < 4; ++op) {
                    float2 r2 = *(const float2*)(red + row * 32 + op * 8 + oc);
                    float2 v = make_float2(acc[mt * 2 + h][op][0] + r2.x + b2[op].x,
                                           acc[mt * 2 + h][op][1] + r2.y + b2[op].y);
                    *(float2*)(out + (size_t)(bBase + row) * OUT_D + op * 8 + oc) = v;
                }
            }
    }
}

// ---------------- launch --------------------------------------------------
extern "C" void kernel_launch(void* const* d_in, const int* in_sizes, int n_in,
                              void* d_out, int out_size) {
    const float* X       = (const float*)d_in[0];
    const float* centers = (const float*)d_in[1];
    const float* sigmas  = (const float*)d_in[2];
    const float* W       = (const float*)d_in[3];
    const float* bias    = (const float*)d_in[4];

    float* out = (float*)d_out;
    float* frs = out + (size_t)B_TOT * OUT_D;

    cudaFuncSetAttribute(kfused, cudaFuncAttributeMaxDynamicSharedMemorySize,
                         SMEM_TOTAL);

    prep_all<<<712, 256>>>(W, centers, sigmas);
    kfused<<<B_TOT / M_CTA, 128, SMEM_TOTAL>>>(X, bias, out, frs);
}

// round 15
// speedup vs baseline: 1.0468x; 1.0468x over previous
#include <cuda_runtime.h>
#include <cuda_fp16.h>
#include <cstdint>

#define B_TOT 16384
#define IN_D  64
#define N_R   128
#define OUT_D 32
#define W_COLS ((IN_D + 1) * N_R)   // 8320

#define N_CHUNK 16
#define RC 8
#define M_CTA 128
#define THREADS 256

// ---------------- device scratch ---------------------------------------
__device__ float g_K0[N_R];                     // sum_i s*c^2
__device__ unsigned int g_Bf[N_CHUNK * 8192];   // pre-swizzled fp16 W tiles
__device__ unsigned int g_WH[2048];             // Wf fp16: 2 halves x [32 o][64 rk]
__device__ unsigned int g_LT[8 * 2048];         // logits tables: 8 stages x 8KB

// ---------------- helpers ------------------------------------------------
#define SWZ(x) ((x) ^ (((x) >> 3) & 0x70))
#define FR_STRIDE 136

__device__ __forceinline__ uint32_t smem_u32(const void* p) {
    uint32_t a;
    asm("{ .reg .u64 t; cvta.to.shared.u64 t, %1; cvt.u32.u64 %0, t; }"
        : "=r"(a) : "l"(p));
    return a;
}
__device__ __forceinline__ void cp16(uint32_t dst, const void* src) {
    uint64_t g;
    asm("cvta.to.global.u64 %0, %1;" : "=l"(g) : "l"(src));
    asm volatile("cp.async.cg.shared.global [%0], [%1], 16;"
                 :: "r"(dst), "l"(g) : "memory");
}
#define CP_COMMIT() asm volatile("cp.async.commit_group;" ::: "memory")
#define CP_WAIT0()  asm volatile("cp.async.wait_group 0;" ::: "memory")

#define LDSM4(r, a) \
    asm volatile("ldmatrix.sync.aligned.m8n8.x4.shared.b16 {%0,%1,%2,%3}, [%4];" \
        : "=r"((r)[0]), "=r"((r)[1]), "=r"((r)[2]), "=r"((r)[3]) : "r"(a))

#define MMA(d, a, b0, b1) \
    asm volatile("mma.sync.aligned.m16n8k16.row.col.f32.f16.f16.f32 " \
        "{%0,%1,%2,%3},{%4,%5,%6,%7},{%8,%9},{%0,%1,%2,%3};" \
        : "+f"((d)[0]), "+f"((d)[1]), "+f"((d)[2]), "+f"((d)[3]) \
        : "r"((a)[0]), "r"((a)[1]), "r"((a)[2]), "r"((a)[3]), \
          "r"(b0), "r"(b1))

// first-touch MMA: d = a*b + 0
#define MMA_Z(d, a, b0, b1) \
    asm volatile("mma.sync.aligned.m16n8k16.row.col.f32.f16.f16.f32 " \
        "{%0,%1,%2,%3},{%4,%5,%6,%7},{%8,%9},{%10,%10,%10,%10};" \
        : "=f"((d)[0]), "=f"((d)[1]), "=f"((d)[2]), "=f"((d)[3]) \
        : "r"((a)[0]), "r"((a)[1]), "r"((a)[2]), "r"((a)[3]), \
          "r"(b0), "r"(b1), "f"(0.0f))

__device__ __forceinline__ unsigned int pack_h2(__half a, __half b) {
    return (unsigned int)__half_as_ushort(a)
         | ((unsigned int)__half_as_ushort(b) << 16);
}

// ---------------- merged prep kernel --------------------------------------
// blocks [0,512): W tiles; [512,520): WfH; [520,584): logits; [584,712): k0
__global__ void __launch_bounds__(256) prep_all(const float* __restrict__ W,
                                                const float* __restrict__ centers,
                                                const float* __restrict__ sigmas) {
    int b = blockIdx.x, tid = threadIdx.x;
    if (b < 512) {
        int idx = b * 256 + tid;            // uint index in [0, 131072)
        int c   = idx >> 13;                // chunk 0..15
        int rem = idx & 8191;               // byte_off = rem*4 = n*128 + k2*4
        int n   = rem >> 5, k2 = rem & 31;  // n 0..255
        int rc  = n >> 5,   o  = n & 31;
        int r   = c * RC + rc;
        int k   = k2 * 2;
        float v0 = W[o * W_COLS + r * IN_D + k];
        float v1 = W[o * W_COLS + r * IN_D + k + 1];
        unsigned int sw = SWZ((unsigned)(rem * 4));
        g_Bf[c * 8192 + (sw >> 2)] = pack_h2(__float2half_rn(v0), __float2half_rn(v1));
    } else if (b < 520) {
        int idx = (b - 512) * 256 + tid;    // [0, 2048)
        int h   = idx >> 10;
        int rem = idx & 1023;
        int o   = rem >> 5, rk2 = rem & 31;
        int r   = h * 64 + rk2 * 2;
        float v0 = W[o * W_COLS + IN_D * N_R + r];
        float v1 = W[o * W_COLS + IN_D * N_R + r + 1];
        unsigned int sw = SWZ((unsigned)(o * 128 + rk2 * 4));
        g_WH[h * 1024 + (sw >> 2)] = pack_h2(__float2half_rn(v0), __float2half_rn(v1));
    } else if (b < 584) {
        int idx = (b - 520) * 256 + tid;    // [0, 16384)
        int s   = idx >> 11;                // stage = tau*2 + half
        int rem = idx & 2047;
        int rr  = rem >> 5, k2 = rem & 31;
        int tau = s >> 1,  h  = s & 1;
        int r   = h * 64 + rr;
        __half vv[2];
#pragma unroll
        for (int e = 0; e < 2; ++e) {
            int i = k2 * 2 + e;
            float sg = sigmas[i * N_R + r];
            float c  = centers[i * N_R + r];
            float s_ = 0.5f / (sg * sg) + 1e-8f;
            float c2 = 2.f * s_ * c;
            if (tau == 0)      vv[e] = __float2half_rn(-s_);
            else if (tau == 1) {
                __half vh = __float2half_rn(-s_);
                vv[e] = __float2half_rn(-s_ - __half2float(vh));
            } else if (tau == 2) vv[e] = __float2half_rn(c2);
            else {
                __half vh = __float2half_rn(c2);
                vv[e] = __float2half_rn(c2 - __half2float(vh));
            }
        }
        g_LT[s * 2048 + (SWZ((unsigned)(rem * 4)) >> 2)] = pack_h2(vv[0], vv[1]);
    } else {
        int r = b - 584;                    // one rule per block
        __shared__ float red[64];
        if (tid < 64) {
            int i = tid;
            float sg = sigmas[i * N_R + r];
            float c  = centers[i * N_R + r];
            float s_ = 0.5f / (sg * sg) + 1e-8f;
            red[i] = s_ * c * c;
        }
        __syncthreads();
        if (tid == 0) {
            float k0 = 0.f;
#pragma unroll
            for (int i = 0; i < 64; ++i) k0 += red[i];
            g_K0[r] = k0;
        }
    }
}

// ---------------- fused kernel (1 CTA/SM, M=128) ---------------------------
// smem map (bytes):
//  [0,16384)        T_xh (A tile, live whole kernel); epilogue: red [128][32]
//  [16384,86016)    logits: T_qh [16K,32K) T_ql [32K,48K) T_xl [48K,64K)
//                   after logits: frs fp32 [128][136] = 69632 B
//  [86016,151552)   logits: LT all 8 stages (64K)
//                   main:   B 2x32K
//                   epilogue: FH fp16 2x16K [86016,118784) + WH 2x4K [118784,..)
//  [151552,152064)  K0 [128] fp32
#define SM_XH 0
#define SM_QH 16384
#define SM_QL 32768
#define SM_XL 49152
#define SM_FR 16384
#define SM_LT 86016
#define SM_B  86016
#define SM_FH 86016
#define SM_WH 118784
#define SM_K0 151552
#define SMEM_TOTAL 152064

__global__ void __launch_bounds__(THREADS, 1) kfused(const float* __restrict__ X,
                                                     const float* __restrict__ bias,
                                                     float* __restrict__ out,
                                                     float* __restrict__ frs) {
    extern __shared__ __align__(1024) char smem[];
    uint32_t sb = smem_u32(smem);
    int tid = threadIdx.x, wid = tid >> 5, lane = tid & 31;
    int bBase = blockIdx.x * M_CTA;

    int lrow = lane & 15, lcol = (lane >> 4) << 4;
    int oc = (lane & 3) << 1;
    int w16 = wid << 4;

    // ---- phase 1: stage ALL logits tables (64K) + K0; build feature tiles
    for (int i = tid; i < 4096; i += THREADS)
        cp16(sb + SM_LT + i * 16, (const char*)g_LT + i * 16);
    if (tid < 32) cp16(sb + SM_K0 + tid * 16, (const char*)g_K0 + tid * 16);
    CP_COMMIT();

    for (int idx = tid; idx < 2048; idx += THREADS) {
        int row = idx >> 4, q = idx & 15;
        float4 v = ((const float4*)(X + (size_t)(bBase + row) * IN_D))[q];
        __half xh[4], xl[4], qh[4], ql[4];
#pragma unroll
        for (int e = 0; e < 4; ++e) {
            float x = (&v.x)[e];
            xh[e] = __float2half_rn(x);
            xl[e] = __float2half_rn(x - __half2float(xh[e]));
            float qf = x * x;
            qh[e] = __float2half_rn(qf);
            ql[e] = __float2half_rn(qf - __half2float(qh[e]));
        }
        unsigned int sw = SWZ((unsigned)(row * 128 + q * 8));
        *(uint2*)(smem + SM_XH + sw) = make_uint2(pack_h2(xh[0], xh[1]), pack_h2(xh[2], xh[3]));
        *(uint2*)(smem + SM_XL + sw) = make_uint2(pack_h2(xl[0], xl[1]), pack_h2(xl[2], xl[3]));
        *(uint2*)(smem + SM_QH + sw) = make_uint2(pack_h2(qh[0], qh[1]), pack_h2(qh[2], qh[3]));
        *(uint2*)(smem + SM_QL + sw) = make_uint2(pack_h2(ql[0], ql[1]), pack_h2(ql[2], ql[3]));
    }
    CP_WAIT0();
    __syncthreads();

    // ---- phase 2: logits via tensor cores — 8 warps, each owns 16 rows
    float dl[16][4];
#pragma unroll
    for (int t = 0; t < 16; ++t)
        dl[t][0] = dl[t][1] = dl[t][2] = dl[t][3] = 0.f;

#pragma unroll
    for (int j = 0; j < 8; ++j) {
        const int tau = j >> 1, h = j & 1;
        const int np = (tau == 0 || tau == 2) ? 2 : 1;
        const uint32_t p0 = (tau < 2) ? SM_QH : SM_XH;
        const uint32_t p1 = (tau == 0) ? SM_QL : SM_XL;
        uint32_t bufS = sb + SM_LT + j * 8192;

#pragma unroll
        for (int ks = 0; ks < 4; ++ks) {
            int col = ks * 32 + lcol;
            uint32_t bF[4][4];
#pragma unroll
            for (int jj = 0; jj < 4; ++jj)
                LDSM4(bF[jj], bufS + SWZ((unsigned)((jj * 16 + lrow) * 128 + col)));
            uint32_t aFr[4];
            LDSM4(aFr, sb + p0 + SWZ((unsigned)((w16 + lrow) * 128 + col)));
#pragma unroll
            for (int jj = 0; jj < 4; ++jj) {
                MMA(dl[h * 8 + 2 * jj],     aFr, bF[jj][0], bF[jj][2]);
                MMA(dl[h * 8 + 2 * jj + 1], aFr, bF[jj][1], bF[jj][3]);
            }
            if (np == 2) {
                uint32_t aF2[4];
                LDSM4(aF2, sb + p1 + SWZ((unsigned)((w16 + lrow) * 128 + col)));
#pragma unroll
                for (int jj = 0; jj < 4; ++jj) {
                    MMA(dl[h * 8 + 2 * jj],     aF2, bF[jj][0], bF[jj][2]);
                    MMA(dl[h * 8 + 2 * jj + 1], aF2, bF[jj][1], bF[jj][3]);
                }
            }
        }
    }
    __syncthreads();                // all LT reads done before B overwrite

    // ---- phase 2.5: issue chunk0 cp.async (32K, overlaps softmax)
    for (int i = tid; i < 2048; i += THREADS)
        cp16(sb + SM_B + i * 16, (const char*)g_Bf + i * 16);
    CP_COMMIT();

    // ---- phase 3: softmax on fragments -> frs fp32 (smem + gmem)
    {
        const float* k0p = (const float*)(smem + SM_K0);
        float mlo = -1e30f, mhi = -1e30f;
#pragma unroll
        for (int t = 0; t < 16; ++t) {
            float2 k2 = *(const float2*)(k0p + t * 8 + oc);
            dl[t][0] -= k2.x; dl[t][1] -= k2.y;
            dl[t][2] -= k2.x; dl[t][3] -= k2.y;
            mlo = fmaxf(mlo, fmaxf(dl[t][0], dl[t][1]));
            mhi = fmaxf(mhi, fmaxf(dl[t][2], dl[t][3]));
        }
#pragma unroll
        for (int off = 1; off < 4; off <<= 1) {
            mlo = fmaxf(mlo, __shfl_xor_sync(0xffffffffu, mlo, off));
            mhi = fmaxf(mhi, __shfl_xor_sync(0xffffffffu, mhi, off));
        }
        float slo = 0.f, shi = 0.f;
#pragma unroll
        for (int t = 0; t < 16; ++t) {
            dl[t][0] = __expf(dl[t][0] - mlo); dl[t][1] = __expf(dl[t][1] - mlo);
            dl[t][2] = __expf(dl[t][2] - mhi); dl[t][3] = __expf(dl[t][3] - mhi);
            slo += dl[t][0] + dl[t][1];
            shi += dl[t][2] + dl[t][3];
        }
#pragma unroll
        for (int off = 1; off < 4; off <<= 1) {
            slo += __shfl_xor_sync(0xffffffffu, slo, off);
            shi += __shfl_xor_sync(0xffffffffu, shi, off);
        }
        float ilo = 1.f / slo, ihi = 1.f / shi;
        int rlo = w16 + (lane >> 2), rhi = rlo + 8;
        float* sFR = (float*)(smem + SM_FR);
#pragma unroll
        for (int t = 0; t < 16; ++t) {
            float2 flo = make_float2(dl[t][0] * ilo, dl[t][1] * ilo);
            float2 fhi = make_float2(dl[t][2] * ihi, dl[t][3] * ihi);
            *(float2*)(sFR + rlo * FR_STRIDE + t * 8 + oc) = flo;
            *(float2*)(sFR + rhi * FR_STRIDE + t * 8 + oc) = fhi;
            *(float2*)(frs + (size_t)(bBase + rlo) * N_R + t * 8 + oc) = flo;
            *(float2*)(frs + (size_t)(bBase + rhi) * N_R + t * 8 + oc) = fhi;
        }
    }
    CP_WAIT0();                     // chunk0 landed
    __syncthreads();

    // ---- main loop: warp grid 4mq x 2nq (m32 each); 16 chunks of 8 rules
    int mq = wid >> 1, nq = wid & 1;
    int rm = mq * 32;

    uint32_t aF[2][4][4];
#pragma unroll
    for (int mt = 0; mt < 2; ++mt)
#pragma unroll
        for (int ks = 0; ks < 4; ++ks) {
            uint32_t offA = SWZ((unsigned)((rm + mt * 16 + lrow) * 128 + ks * 32 + lcol));
            LDSM4(aF[mt][ks], sb + SM_XH + offA);
        }
    uint32_t colS[4];
    {
        unsigned xr = ((unsigned)(lrow & 7)) << 4;
#pragma unroll
        for (int ks = 0; ks < 4; ++ks)
            colS[ks] = ((unsigned)(ks * 32 + lcol)) ^ xr;
    }
    uint32_t rowB0 = (unsigned)(nq * 128 + lrow) * 128;

    float acc[4][4][2];
#pragma unroll
    for (int a = 0; a < 4; ++a)
#pragma unroll
        for (int b = 0; b < 4; ++b) acc[a][b][0] = acc[a][b][1] = 0.f;

    const float* sFR = (const float*)(smem + SM_FR);

    for (int c = 0; c < N_CHUNK; ++c) {
        int cur = c & 1, nxt = cur ^ 1;

        if (c + 1 < N_CHUNK) {
            const char* gsrc = (const char*)(g_Bf + (c + 1) * 8192);
            uint32_t dd = sb + SM_B + nxt * 32768;
            for (int i = tid; i < 2048; i += THREADS) cp16(dd + i * 16, gsrc + i * 16);
        }
        CP_COMMIT();

        float4 f4[2][2];
#pragma unroll
        for (int mt = 0; mt < 2; ++mt)
#pragma unroll
            for (int h = 0; h < 2; ++h) {
                int row = rm + mt * 16 + (lane >> 2) + h * 8;
                f4[mt][h] = *(const float4*)(sFR + row * FR_STRIDE + c * RC + nq * 4);
            }

        uint32_t bufB = sb + SM_B + cur * 32768 + rowB0;
#pragma unroll
        for (int tp = 0; tp < 8; ++tp) {
            float d[2][2][4];
#pragma unroll
            for (int ks = 0; ks < 4; ++ks) {
                uint32_t bH[4];
                LDSM4(bH, bufB + tp * 2048 + colS[ks]);
#pragma unroll
                for (int mt = 0; mt < 2; ++mt) {
                    if (ks == 0) {
                        MMA_Z(d[mt][0], aF[mt][ks], bH[0], bH[2]);
                        MMA_Z(d[mt][1], aF[mt][ks], bH[1], bH[3]);
                    } else {
                        MMA(d[mt][0], aF[mt][ks], bH[0], bH[2]);
                        MMA(d[mt][1], aF[mt][ks], bH[1], bH[3]);
                    }
                }
            }
            const int rs = tp >> 1;
#pragma unroll
            for (int mt = 0; mt < 2; ++mt)
#pragma unroll
                for (int n8 = 0; n8 < 2; ++n8) {
                    int op = ((tp & 1) << 1) + n8;
#pragma unroll
                    for (int h = 0; h < 2; ++h) {
                        float fl = (&f4[mt][h].x)[rs];
                        acc[mt * 2 + h][op][0] = fmaf(fl, d[mt][n8][2 * h],     acc[mt * 2 + h][op][0]);
                        acc[mt * 2 + h][op][1] = fmaf(fl, d[mt][n8][2 * h + 1], acc[mt * 2 + h][op][1]);
                    }
                }
        }

        CP_WAIT0();
        __syncthreads();
    }

    // ---- epilogue A: rebuild FH (fp16 frs, [2 halves][128 rows][64 rk])
    for (int i = tid; i < 512; i += THREADS)
        cp16(sb + SM_WH + i * 16, (const char*)g_WH + i * 16);
    CP_COMMIT();
    for (int i = tid; i < 8192; i += THREADS) {
        int h   = i >> 12;
        int rem = i & 4095;
        int row = rem >> 5, rk2 = rem & 31;
        float2 fv = *(const float2*)(sFR + row * FR_STRIDE + h * 64 + rk2 * 2);
        *(uint32_t*)(smem + SM_FH + h * 16384 + SWZ((unsigned)(row * 128 + rk2 * 4))) =
            pack_h2(__float2half_rn(fv.x), __float2half_rn(fv.y));
    }
    CP_WAIT0();
    __syncthreads();

    // ---- epilogue B: rule-bias GEMM  acc += frs_h(nq) @ WfH(nq)
    {
        uint32_t fhBase = sb + SM_FH + nq * 16384;
        uint32_t whBase = sb + SM_WH + nq * 4096;
        float dW[2][2][2][4];
#pragma unroll
        for (int ks = 0; ks < 4; ++ks) {
            uint32_t aFr[2][4];
#pragma unroll
            for (int mt = 0; mt < 2; ++mt)
                LDSM4(aFr[mt], fhBase + SWZ((unsigned)((rm + mt * 16 + lrow) * 128 + ks * 32 + lcol)));
#pragma unroll
            for (int tp = 0; tp < 2; ++tp) {
                uint32_t bW[4];
                LDSM4(bW, whBase + SWZ((unsigned)((tp * 16 + lrow) * 128 + ks * 32 + lcol)));
#pragma unroll
                for (int mt = 0; mt < 2; ++mt) {
                    if (ks == 0) {
                        MMA_Z(dW[mt][tp][0], aFr[mt], bW[0], bW[2]);
                        MMA_Z(dW[mt][tp][1], aFr[mt], bW[1], bW[3]);
                    } else {
                        MMA(dW[mt][tp][0], aFr[mt], bW[0], bW[2]);
                        MMA(dW[mt][tp][1], aFr[mt], bW[1], bW[3]);
                    }
                }
            }
        }
#pragma unroll
        for (int mt = 0; mt < 2; ++mt)
#pragma unroll
            for (int tp = 0; tp < 2; ++tp)
#pragma unroll
                for (int n8 = 0; n8 < 2; ++n8)
#pragma unroll
                    for (int h = 0; h < 2; ++h) {
                        acc[mt * 2 + h][tp * 2 + n8][0] += dW[mt][tp][n8][2 * h];
                        acc[mt * 2 + h][tp * 2 + n8][1] += dW[mt][tp][n8][2 * h + 1];
                    }
    }

    // ---- epilogue C: reduce nq pair via smem (T_xh dead), + bias, store
    __syncthreads();
    float* red = (float*)smem;            // [128][32] fp32 = 16 KB
    if (nq == 1) {
#pragma unroll
        for (int mt = 0; mt < 2; ++mt)
#pragma unroll
            for (int h = 0; h < 2; ++h) {
                int row = rm + mt * 16 + (lane >> 2) + h * 8;
#pragma unroll
                for (int op = 0; op < 4; ++op)
                    *(float2*)(red + row * 32 + op * 8 + oc) =
                        make_float2(acc[mt * 2 + h][op][0], acc[mt * 2 + h][op][1]);
            }
    }
    __syncthreads();
    if (nq == 0) {
        float2 b2[4];
#pragma unroll
        for (int op = 0; op < 4; ++op)
            b2[op] = *(const float2*)(bias + op * 8 + oc);
#pragma unroll
        for (int mt = 0; mt < 2; ++mt)
#pragma unroll
            for (int h = 0; h < 2; ++h) {
                int row = rm + mt * 16 + (lane >> 2) + h * 8;
#pragma unroll
                for (int op = 0; op < 4; ++op) {
                    float2 r2 = *(const float2*)(red + row * 32 + op * 8 + oc);
                    float2 v = make_float2(acc[mt * 2 + h][op][0] + r2.x + b2[op].x,
                                           acc[mt * 2 + h][op][1] + r2.y + b2[op].y);
                    *(float2*)(out + (size_t)(bBase + row) * OUT_D + op * 8 + oc) = v;
                }
            }
    }
}

// ---------------- launch --------------------------------------------------
extern "C" void kernel_launch(void* const* d_in, const int* in_sizes, int n_in,
                              void* d_out, int out_size) {
    const float* X       = (const float*)d_in[0];
    const float* centers = (const float*)d_in[1];
    const float* sigmas  = (const float*)d_in[2];
    const float* W       = (const float*)d_in[3];
    const float* bias    = (const float*)d_in[4];

    float* out = (float*)d_out;
    float* frs = out + (size_t)B_TOT * OUT_D;

    cudaFuncSetAttribute(kfused, cudaFuncAttributeMaxDynamicSharedMemorySize,
                         SMEM_TOTAL);

    prep_all<<<712, 256>>>(W, centers, sigmas);
    kfused<<<B_TOT / M_CTA, THREADS, SMEM_TOTAL>>>(X, bias, out, frs);
}